// round 14
// baseline (speedup 1.0000x reference)
#include <cuda_runtime.h>
#include <cstdint>

// Problem constants (fixed by setup_inputs)
#define B_   8
#define C_   64
#define H_   128
#define W_   512
#define SATW 512
#define HALF 256
#define NPIX (B_*H_*W_)          // 524288
#define CELLS (B_*SATW*SATW)     // 2097152

__device__ float               g_kinv[B_*9];
__device__ unsigned int        g_maxy_ord;
__device__ unsigned long long  g_cellkey[CELLS];    // 16 MB
__device__ float               g_nhwc[NPIX*64];     // 134 MB: image as (b,pix,c)

// Monotonic float -> uint mapping (order preserving)
__device__ __forceinline__ unsigned int ford(float f) {
    unsigned int u = __float_as_uint(f);
    return (u & 0x80000000u) ? ~u : (u | 0x80000000u);
}
__device__ __forceinline__ float ford_inv(unsigned int o) {
    unsigned int u = (o & 0x80000000u) ? (o & 0x7FFFFFFFu) : ~o;
    return __uint_as_float(u);
}

// ---------------------------------------------------------------------------
// K0: per-replay reset (cell keys + max) + per-batch scaled-K inverse.
// Adjugate inverse matches the LU-based reference bitwise for this matrix
// structure (rel_err = 0 across R1-R13).
// ---------------------------------------------------------------------------
__global__ void k_init(const float* __restrict__ ck) {
    int i = blockIdx.x * blockDim.x + threadIdx.x;
    if (i < CELLS) g_cellkey[i] = 0ull;
    if (blockIdx.x == 0 && threadIdx.x < 32) {
        int b = threadIdx.x;
        if (b == 0) g_maxy_ord = 0u;
        if (b < B_) {
            const float rs0 = (float)W_ / 1024.0f;
            const float rs1 = (float)H_ / 256.0f;
            float a[9];
            #pragma unroll
            for (int r = 0; r < 3; r++) {
                float s = (r == 0) ? rs0 : (r == 1) ? rs1 : 1.0f;
                #pragma unroll
                for (int cc = 0; cc < 3; cc++)
                    a[r*3+cc] = __fmul_rn(ck[b*9 + r*3 + cc], s);
            }
            float c00 = a[4]*a[8] - a[5]*a[7];
            float c01 = a[5]*a[6] - a[3]*a[8];
            float c02 = a[3]*a[7] - a[4]*a[6];
            float det = a[0]*c00 + a[1]*c01 + a[2]*c02;
            float inv[9];
            inv[0] = __fdiv_rn(c00, det);
            inv[1] = __fdiv_rn(a[2]*a[7] - a[1]*a[8], det);
            inv[2] = __fdiv_rn(a[1]*a[5] - a[2]*a[4], det);
            inv[3] = __fdiv_rn(c01, det);
            inv[4] = __fdiv_rn(a[0]*a[8] - a[2]*a[6], det);
            inv[5] = __fdiv_rn(a[2]*a[3] - a[0]*a[5], det);
            inv[6] = __fdiv_rn(c02, det);
            inv[7] = __fdiv_rn(a[1]*a[6] - a[0]*a[7], det);
            inv[8] = __fdiv_rn(a[0]*a[4] - a[1]*a[3], det);
            #pragma unroll
            for (int k = 0; k < 9; k++) g_kinv[b*9 + k] = inv[k];
        }
    }
}

// ---------------------------------------------------------------------------
// K_T: NCHW -> NHWC transpose, vectorized (LDG.128 / STG.128), smem [c][65].
// 8192 blocks on the forked stream, overlapping the point pipeline.
// ---------------------------------------------------------------------------
__global__ void __launch_bounds__(256) k_T(const float* __restrict__ image) {
    __shared__ float st[64][65];
    int b  = blockIdx.x >> 10;
    int pt = (blockIdx.x & 1023) << 6;
    int tid = threadIdx.x;

    const float* src = image + ((size_t)b << 22) + pt;   // + c*65536 + p
    #pragma unroll
    for (int it = 0; it < 4; it++) {
        int idx = (it << 8) + tid;        // 0..1023
        int c   = idx >> 4;
        int p4  = (idx & 15) << 2;
        float4 v = __ldg(reinterpret_cast<const float4*>(
            src + ((size_t)c << 16) + p4));
        st[c][p4]     = v.x;
        st[c][p4 + 1] = v.y;
        st[c][p4 + 2] = v.z;
        st[c][p4 + 3] = v.w;
    }
    __syncthreads();
    float* dst = g_nhwc + (((size_t)(b << 16) + pt) << 6);  // + p*64 + c
    #pragma unroll
    for (int it = 0; it < 4; it++) {
        int idx = (it << 8) + tid;
        int p   = idx >> 4;
        int c4  = (idx & 15) << 2;
        float4 v;
        v.x = st[c4][p];
        v.y = st[c4 + 1][p];
        v.z = st[c4 + 2][p];
        v.w = st[c4 + 3][p];
        *reinterpret_cast<float4*>(dst + ((size_t)p << 6) + c4) = v;
    }
}

// ---------------------------------------------------------------------------
// Shared per-point geometry (exact op order vs reference; no fma contraction)
// -- R11 version, untouched (pow2 experiments regressed; reverted).
// ---------------------------------------------------------------------------
struct Pt { int x, z; float y; bool kept; };

__device__ __forceinline__ Pt compute_pt(int i, const float* __restrict__ depth,
                                         float mpp) {
    int b   = i >> 16;           // H*W = 65536
    int pix = i & 0xFFFF;
    float v = (float)(pix >> 9); // W = 512
    float u = (float)(pix & 511);
    const float* K = &g_kinv[b*9];
    float xw = __fadd_rn(__fadd_rn(__fmul_rn(K[0], u), __fmul_rn(K[1], v)), K[2]);
    float yw = __fadd_rn(__fadd_rn(__fmul_rn(K[3], u), __fmul_rn(K[4], v)), K[5]);
    float zw = __fadd_rn(__fadd_rn(__fmul_rn(K[6], u), __fmul_rn(K[7], v)), K[8]);
    float d  = __ldg(depth + i);
    float X  = __fmul_rn(__fmul_rn(xw, d), 1.2f);
    float Y  = __fmul_rn(__fmul_rn(yw, d), 1.2f);
    float Z  = __fmul_rn(__fmul_rn(zw, d), 1.2f);
    int xi = (int)__fdiv_rn(X, mpp);
    int zi = (int)__fdiv_rn(Z, mpp);
    Pt p;
    p.x = xi; p.z = zi; p.y = Y;
    p.kept = (xi >= -HALF) && (xi <= HALF-1) && (zi >= -HALF) && (zi <= HALF-1);
    return p;
}

// ---------------------------------------------------------------------------
// K1: global max of y over kept points
// ---------------------------------------------------------------------------
__global__ void k_maxy(const float* __restrict__ depth,
                       const float* __restrict__ mpp_p) {
    int i = blockIdx.x * blockDim.x + threadIdx.x;
    unsigned int o = 0u;
    if (i < NPIX) {
        Pt p = compute_pt(i, depth, __ldg(mpp_p));
        if (p.kept) o = ford(p.y);
    }
    o = __reduce_max_sync(0xFFFFFFFFu, o);
    if ((threadIdx.x & 31) == 0 && o != 0u) atomicMax(&g_maxy_ord, o);
}

// ---------------------------------------------------------------------------
// K2: per-point atomicMax of packed key (ordered(h)<<16 | pixel_index).
// Reproduces lexsort((h, rank)) + is_last selection exactly (ties included).
// ---------------------------------------------------------------------------
__global__ void k_scatter(const float* __restrict__ depth,
                          const float* __restrict__ mpp_p) {
    int i = blockIdx.x * blockDim.x + threadIdx.x;
    if (i >= NPIX) return;
    Pt p = compute_pt(i, depth, __ldg(mpp_p));
    if (!p.kept) return;
    float max_h = ford_inv(g_maxy_ord);
    float h = __fadd_rn(max_h, -p.y);
    int b   = i >> 16;
    int pix = i & 0xFFFF;
    unsigned long long key =
        ((unsigned long long)ford(h) << 16) | (unsigned long long)pix;
    int xx = p.x + HALF, zz = p.z + HALF;
    int cell = ((b * SATW) + xx) * SATW + zz;
    atomicMax(&g_cellkey[cell], key);
}

// ---------------------------------------------------------------------------
// K_O: output pass. Block = (b, xx, 128-zz tile); 16384 blocks.
// Staging split into even/odd channel tiles so BOTH smem directions are
// bank-conflict-free:
//   fill: te[zz][lane]=v.x (c=2*lane), to[zz][lane]=v.y (c=2*lane+1)
//         -> lane stride 1, conflict-free STS (was 2-way conflicted)
//   emit: warp-uniform c reads t?[zz][c>>1], lane stride 33 (odd)
//         -> conflict-free LDS, then coalesced streaming STG.
// ---------------------------------------------------------------------------
__global__ void __launch_bounds__(256) k_O(float* __restrict__ out) {
    __shared__ float te[128][33];    // even channels: c = 2*j
    __shared__ float to[128][33];    // odd channels:  c = 2*j+1
    int bid = blockIdx.x;                 // (b<<11) | (xx<<2) | zq
    int b  = bid >> 11;
    int xx = (bid >> 2) & 511;
    int zt = (bid & 3) << 7;
    int w = threadIdx.x >> 5, lane = threadIdx.x & 31;

    const unsigned long long* wn = g_cellkey + ((b << 18) + (xx << 9) + zt);
    const float2* nb = reinterpret_cast<const float2*>(g_nhwc)
                       + ((size_t)(b << 16) << 5);        // + pix*32 + lane
    #pragma unroll
    for (int k = 0; k < 16; k++) {
        int zz = (w << 4) + k;
        unsigned long long key = __ldcs(wn + zz);
        float2 v = make_float2(0.0f, 0.0f);
        if (key) {
            int pix = (int)(key & 0xFFFFull);
            v = __ldg(nb + (((size_t)pix) << 5) + lane);
        }
        te[zz][lane] = v.x;
        to[zz][lane] = v.y;
    }
    __syncthreads();

    // out element: ((b*64 + c) << 18) + (xx << 9) + zt + zz
    // c is warp-uniform per step; lanes sweep zz (stride 33 -> conflict-free).
    size_t base = ((size_t)b << 24) + ((size_t)xx << 9) + (size_t)zt;
    #pragma unroll
    for (int it = 0; it < 32; it++) {
        int e  = (it << 8) + threadIdx.x;
        int c  = e >> 7;
        int zz = e & 127;
        float val = (c & 1) ? to[zz][c >> 1] : te[zz][c >> 1];
        __stcs(out + base + ((size_t)c << 18) + zz, val);
    }
}

// ---------------------------------------------------------------------------
extern "C" void kernel_launch(void* const* d_in, const int* in_sizes, int n_in,
                              void* d_out, int out_size) {
    const float* image = (const float*)d_in[0];   // (B,C,H,W) f32
    const float* ck    = (const float*)d_in[1];   // (B,3,3)   f32
    const float* depth = (const float*)d_in[2];   // (B,H,W)   f32
    const float* mpp   = (const float*)d_in[3];   // (1,)      f32
    float* out = (float*)d_out;

    // R11 single-fork structure (proven best): side stream does the 268 MB
    // transpose, main runs the point pipeline, then the big emit after join.
    // (Handles created here are bounded — kernel_launch runs only for
    // correctness + capture; no device memory is allocated.)
    cudaStream_t s2;
    cudaEvent_t eFork, eJoin;
    cudaStreamCreateWithFlags(&s2, cudaStreamNonBlocking);
    cudaEventCreateWithFlags(&eFork, cudaEventDisableTiming);
    cudaEventCreateWithFlags(&eJoin, cudaEventDisableTiming);

    cudaEventRecord(eFork, 0);
    cudaStreamWaitEvent(s2, eFork, 0);
    k_T<<<B_ * 1024, 256, 0, s2>>>(image);        // branch: 268 MB transpose

    k_init<<<CELLS / 256, 256>>>(ck);             // main: reset + kinv
    k_maxy<<<NPIX / 256, 256>>>(depth, mpp);      // main: global max
    k_scatter<<<NPIX / 256, 256>>>(depth, mpp);   // main: winner keys

    cudaEventRecord(eJoin, s2);
    cudaStreamWaitEvent(0, eJoin, 0);

    k_O<<<CELLS / 128, 256>>>(out);               // big emit
    (void)in_sizes; (void)n_in; (void)out_size;
}

// round 15
// speedup vs baseline: 1.0911x; 1.0911x over previous
#include <cuda_runtime.h>
#include <cstdint>

// Problem constants (fixed by setup_inputs)
#define B_   8
#define C_   64
#define H_   128
#define W_   512
#define SATW 512
#define HALF 256
#define NPIX (B_*H_*W_)          // 524288
#define CELLS (B_*SATW*SATW)     // 2097152

__device__ float               g_kinv[B_*9];
__device__ unsigned int        g_maxy_ord;
__device__ unsigned long long  g_cellkey[CELLS];    // 16 MB
__device__ float               g_nhwc[NPIX*64];     // 134 MB: image as (b,pix,c)

// Monotonic float -> uint mapping (order preserving)
__device__ __forceinline__ unsigned int ford(float f) {
    unsigned int u = __float_as_uint(f);
    return (u & 0x80000000u) ? ~u : (u | 0x80000000u);
}
__device__ __forceinline__ float ford_inv(unsigned int o) {
    unsigned int u = (o & 0x80000000u) ? (o & 0x7FFFFFFFu) : ~o;
    return __uint_as_float(u);
}

// ---------------------------------------------------------------------------
// K0: per-replay reset (cell keys + max) + per-batch scaled-K inverse.
// Adjugate inverse matches the LU-based reference bitwise for this matrix
// structure (rel_err = 0 across R1-R14).
// ---------------------------------------------------------------------------
__global__ void k_init(const float* __restrict__ ck) {
    int i = blockIdx.x * blockDim.x + threadIdx.x;
    if (i < CELLS) g_cellkey[i] = 0ull;
    if (blockIdx.x == 0 && threadIdx.x < 32) {
        int b = threadIdx.x;
        if (b == 0) g_maxy_ord = 0u;
        if (b < B_) {
            const float rs0 = (float)W_ / 1024.0f;
            const float rs1 = (float)H_ / 256.0f;
            float a[9];
            #pragma unroll
            for (int r = 0; r < 3; r++) {
                float s = (r == 0) ? rs0 : (r == 1) ? rs1 : 1.0f;
                #pragma unroll
                for (int cc = 0; cc < 3; cc++)
                    a[r*3+cc] = __fmul_rn(ck[b*9 + r*3 + cc], s);
            }
            float c00 = a[4]*a[8] - a[5]*a[7];
            float c01 = a[5]*a[6] - a[3]*a[8];
            float c02 = a[3]*a[7] - a[4]*a[6];
            float det = a[0]*c00 + a[1]*c01 + a[2]*c02;
            float inv[9];
            inv[0] = __fdiv_rn(c00, det);
            inv[1] = __fdiv_rn(a[2]*a[7] - a[1]*a[8], det);
            inv[2] = __fdiv_rn(a[1]*a[5] - a[2]*a[4], det);
            inv[3] = __fdiv_rn(c01, det);
            inv[4] = __fdiv_rn(a[0]*a[8] - a[2]*a[6], det);
            inv[5] = __fdiv_rn(a[2]*a[3] - a[0]*a[5], det);
            inv[6] = __fdiv_rn(c02, det);
            inv[7] = __fdiv_rn(a[1]*a[6] - a[0]*a[7], det);
            inv[8] = __fdiv_rn(a[0]*a[4] - a[1]*a[3], det);
            #pragma unroll
            for (int k = 0; k < 9; k++) g_kinv[b*9 + k] = inv[k];
        }
    }
}

// ---------------------------------------------------------------------------
// K_T: NCHW -> NHWC transpose, vectorized (LDG.128 / STG.128), smem [c][65].
// 8192 blocks on the forked stream, overlapping the point pipeline.
// ---------------------------------------------------------------------------
__global__ void __launch_bounds__(256) k_T(const float* __restrict__ image) {
    __shared__ float st[64][65];
    int b  = blockIdx.x >> 10;
    int pt = (blockIdx.x & 1023) << 6;
    int tid = threadIdx.x;

    const float* src = image + ((size_t)b << 22) + pt;   // + c*65536 + p
    #pragma unroll
    for (int it = 0; it < 4; it++) {
        int idx = (it << 8) + tid;        // 0..1023
        int c   = idx >> 4;
        int p4  = (idx & 15) << 2;
        float4 v = __ldg(reinterpret_cast<const float4*>(
            src + ((size_t)c << 16) + p4));
        st[c][p4]     = v.x;
        st[c][p4 + 1] = v.y;
        st[c][p4 + 2] = v.z;
        st[c][p4 + 3] = v.w;
    }
    __syncthreads();
    float* dst = g_nhwc + (((size_t)(b << 16) + pt) << 6);  // + p*64 + c
    #pragma unroll
    for (int it = 0; it < 4; it++) {
        int idx = (it << 8) + tid;
        int p   = idx >> 4;
        int c4  = (idx & 15) << 2;
        float4 v;
        v.x = st[c4][p];
        v.y = st[c4 + 1][p];
        v.z = st[c4 + 2][p];
        v.w = st[c4 + 3][p];
        *reinterpret_cast<float4*>(dst + ((size_t)p << 6) + c4) = v;
    }
}

// ---------------------------------------------------------------------------
// Shared per-point geometry (exact op order vs reference; no fma contraction)
// -- R11 version, untouched.
// ---------------------------------------------------------------------------
struct Pt { int x, z; float y; bool kept; };

__device__ __forceinline__ Pt compute_pt(int i, const float* __restrict__ depth,
                                         float mpp) {
    int b   = i >> 16;           // H*W = 65536
    int pix = i & 0xFFFF;
    float v = (float)(pix >> 9); // W = 512
    float u = (float)(pix & 511);
    const float* K = &g_kinv[b*9];
    float xw = __fadd_rn(__fadd_rn(__fmul_rn(K[0], u), __fmul_rn(K[1], v)), K[2]);
    float yw = __fadd_rn(__fadd_rn(__fmul_rn(K[3], u), __fmul_rn(K[4], v)), K[5]);
    float zw = __fadd_rn(__fadd_rn(__fmul_rn(K[6], u), __fmul_rn(K[7], v)), K[8]);
    float d  = __ldg(depth + i);
    float X  = __fmul_rn(__fmul_rn(xw, d), 1.2f);
    float Y  = __fmul_rn(__fmul_rn(yw, d), 1.2f);
    float Z  = __fmul_rn(__fmul_rn(zw, d), 1.2f);
    int xi = (int)__fdiv_rn(X, mpp);
    int zi = (int)__fdiv_rn(Z, mpp);
    Pt p;
    p.x = xi; p.z = zi; p.y = Y;
    p.kept = (xi >= -HALF) && (xi <= HALF-1) && (zi >= -HALF) && (zi <= HALF-1);
    return p;
}

// ---------------------------------------------------------------------------
// K1: global max of y over kept points
// ---------------------------------------------------------------------------
__global__ void k_maxy(const float* __restrict__ depth,
                       const float* __restrict__ mpp_p) {
    int i = blockIdx.x * blockDim.x + threadIdx.x;
    unsigned int o = 0u;
    if (i < NPIX) {
        Pt p = compute_pt(i, depth, __ldg(mpp_p));
        if (p.kept) o = ford(p.y);
    }
    o = __reduce_max_sync(0xFFFFFFFFu, o);
    if ((threadIdx.x & 31) == 0 && o != 0u) atomicMax(&g_maxy_ord, o);
}

// ---------------------------------------------------------------------------
// K2: per-point atomicMax of packed key (ordered(h)<<16 | pixel_index).
// Reproduces lexsort((h, rank)) + is_last selection exactly (ties included).
// ---------------------------------------------------------------------------
__global__ void k_scatter(const float* __restrict__ depth,
                          const float* __restrict__ mpp_p) {
    int i = blockIdx.x * blockDim.x + threadIdx.x;
    if (i >= NPIX) return;
    Pt p = compute_pt(i, depth, __ldg(mpp_p));
    if (!p.kept) return;
    float max_h = ford_inv(g_maxy_ord);
    float h = __fadd_rn(max_h, -p.y);
    int b   = i >> 16;
    int pix = i & 0xFFFF;
    unsigned long long key =
        ((unsigned long long)ford(h) << 16) | (unsigned long long)pix;
    int xx = p.x + HALF, zz = p.z + HALF;
    int cell = ((b * SATW) + xx) * SATW + zz;
    atomicMax(&g_cellkey[cell], key);
}

// ---------------------------------------------------------------------------
// K_O: output pass. Block = (b, xx, 64-zz tile); 32768 blocks.
// Tile halved vs R11 ([64][65] = 16.6 KB smem) -> 8 blocks/SM = 64 warps =
// 100% occupancy (was 75%) to hide the gather latency; finer wave balance.
// Access patterns identical to the proven R11 kernel: nonempty cell -> ONE
// coalesced 256 B float2/lane vector load; emit reads tile[zz][c] with lane
// stride 65 (conflict-free) and writes coalesced 128 B streaming stores.
// ---------------------------------------------------------------------------
__global__ void __launch_bounds__(256) k_O(float* __restrict__ out) {
    __shared__ float tile[64][65];
    int bid = blockIdx.x;                 // (b<<12) | (xx<<3) | zo
    int b  = bid >> 12;
    int xx = (bid >> 3) & 511;
    int zt = (bid & 7) << 6;
    int w = threadIdx.x >> 5, lane = threadIdx.x & 31;

    const unsigned long long* wn = g_cellkey + ((b << 18) + (xx << 9) + zt);
    const float2* nb = reinterpret_cast<const float2*>(g_nhwc)
                       + ((size_t)(b << 16) << 5);        // + pix*32 + lane
    #pragma unroll
    for (int k = 0; k < 8; k++) {
        int zz = (w << 3) + k;
        unsigned long long key = __ldcs(wn + zz);
        float2 v = make_float2(0.0f, 0.0f);
        if (key) {
            int pix = (int)(key & 0xFFFFull);
            v = __ldg(nb + (((size_t)pix) << 5) + lane);
        }
        tile[zz][lane * 2]     = v.x;
        tile[zz][lane * 2 + 1] = v.y;
    }
    __syncthreads();

    // out element: ((b*64 + c) << 18) + (xx << 9) + zt + zz
    // c warp-uniform per step; lanes sweep zz (stride 65 -> conflict-free).
    size_t base = ((size_t)b << 24) + ((size_t)xx << 9) + (size_t)zt;
    #pragma unroll
    for (int it = 0; it < 16; it++) {
        int e  = (it << 8) + threadIdx.x;   // 0..4095 = 64c x 64zz
        int c  = e >> 6;
        int zz = e & 63;
        __stcs(out + base + ((size_t)c << 18) + zz, tile[zz][c]);
    }
}

// ---------------------------------------------------------------------------
extern "C" void kernel_launch(void* const* d_in, const int* in_sizes, int n_in,
                              void* d_out, int out_size) {
    const float* image = (const float*)d_in[0];   // (B,C,H,W) f32
    const float* ck    = (const float*)d_in[1];   // (B,3,3)   f32
    const float* depth = (const float*)d_in[2];   // (B,H,W)   f32
    const float* mpp   = (const float*)d_in[3];   // (1,)      f32
    float* out = (float*)d_out;

    // R11 single-fork structure (proven best): side stream does the 268 MB
    // transpose, main runs the point pipeline, then the big emit after join.
    // (Handles created here are bounded — kernel_launch runs only for
    // correctness + capture; no device memory is allocated.)
    cudaStream_t s2;
    cudaEvent_t eFork, eJoin;
    cudaStreamCreateWithFlags(&s2, cudaStreamNonBlocking);
    cudaEventCreateWithFlags(&eFork, cudaEventDisableTiming);
    cudaEventCreateWithFlags(&eJoin, cudaEventDisableTiming);

    cudaEventRecord(eFork, 0);
    cudaStreamWaitEvent(s2, eFork, 0);
    k_T<<<B_ * 1024, 256, 0, s2>>>(image);        // branch: 268 MB transpose

    k_init<<<CELLS / 256, 256>>>(ck);             // main: reset + kinv
    k_maxy<<<NPIX / 256, 256>>>(depth, mpp);      // main: global max
    k_scatter<<<NPIX / 256, 256>>>(depth, mpp);   // main: winner keys

    cudaEventRecord(eJoin, s2);
    cudaStreamWaitEvent(0, eJoin, 0);

    k_O<<<CELLS / 64, 256>>>(out);                // big emit, 100% occ
    (void)in_sizes; (void)n_in; (void)out_size;
}